// round 6
// baseline (speedup 1.0000x reference)
#include <cuda_runtime.h>
#include <math.h>

#define BSZ 256
#define IND 64
#define HID 128
#define NB 50
#define S1 51
#define ROWS (S1 * S1)          // 2601
#define ST 136                  // segment row stride in floats (= 34 float4)
#define NK4 34
#define SEGF (129 * ST)         // 17544 floats per b per array
#define CPB 4                   // quad chunks per batch element
#define PPC ((ROWS + CPB - 1) / CPB)   // 651
#define PI_D 3.14159265358979323846

// ---------------- global scratch (static device arrays) ----------------
__device__ float g_steps[S1];
__device__ float g_cc[S1];
__device__ float g_xmax;
__device__ int   g_iperm[HID];
__device__ int   g_npos;
__device__ int   g_nposp;
__device__ float g_A[BSZ * SEGF];       // ~18 MB (L2-resident)
__device__ float g_Bv[BSZ * SEGF];      // ~18 MB
__device__ float g_bp[BSZ * HID];       // sorted breakpoints per b
__device__ float g_part[BSZ * CPB];     // per-chunk deterministic partials
__device__ float g_osc[BSZ * 2];        // offset, log-scale per b

// ===================== prep =====================
__global__ void prep_kernel(const float* __restrict__ x, const float* __restrict__ iw2) {
    __shared__ float st_s[S1];
    __shared__ double part[256];
    __shared__ float red[256];
    int tx = threadIdx.x;
    if (tx < S1) {
        double st = cos((double)tx * PI_D / (double)NB);
        st_s[tx] = (float)st;
        g_steps[tx] = (float)st;
    }
    double p = 0.0;
    if (tx < 255) {
        int c = tx / 5, u = tx % 5;
        for (int ie = u; ie < 26; ie += 5) {
            int i = 2 * ie;
            double W = (i == 0) ? 1.0 : 2.0 / (1.0 - (double)i * (double)i);
            double l;
            if (c == 0) l = 0.5;
            else {
                l = cos((double)i * (double)c * PI_D / (double)NB);
                if (c == NB) l *= 0.5;
            }
            p += l * (2.0 / (double)NB) * W;
        }
    }
    part[tx] = p;
    __syncthreads();
    if (tx < S1) {
        double s = 0.0;
        for (int u = 0; u < 5; u++) s += part[tx * 5 + u];
        g_cc[tx] = (float)s;
    }
    float mx = -3.0e38f;
    if (tx < BSZ) {
        float xb = x[tx];
        for (int i = 0; i < S1; i++)
            mx = fmaxf(mx, xb * (st_s[i] + 1.0f) * 0.5f);
    }
    red[tx] = mx;
    __syncthreads();
    for (int o = 128; o > 0; o >>= 1) {
        if (tx < o) red[tx] = fmaxf(red[tx], red[tx + o]);
        __syncthreads();
    }
    if (tx == 0) {
        g_xmax = red[0] + 10.0f;
        int P = 0;
        for (int k = 0; k < HID; k++) if (iw2[k] >= 0.0f) g_iperm[k] = P++;
        g_npos = P;
        int Pp = (P + 3) & ~3;
        g_nposp = Pp;
        int Q = Pp;
        for (int k = 0; k < HID; k++) if (iw2[k] < 0.0f)  g_iperm[k] = Q++;
    }
}

// ===================== build: per-b setup -> segments/bp/osc to global =====================
// dynamic smem layout (floats)
#define BW_W     0              // 16384: iw1 * iw2[k] prefolded
#define BW_H     16384          // 64
#define BW_BASE  (BW_H + 64)    // 128
#define BW_W0    (BW_BASE + 128)
#define BW_BP    (BW_W0 + 128)
#define BW_MI    (BW_BP + 128)  // 128 ints
#define BW_IW2   (BW_MI + 128)  // 128
#define BW_A1    (BW_IW2 + 128) // 128 (nmlp scratch)
#define BW_A2    (BW_A1 + 128)  // 128
#define BW_RED   (BW_A2 + 128)  // 8
#define BW_TOT   (BW_RED + 8)   // 17232 floats = 68928 B

__global__ void __launch_bounds__(256, 2)
build_kernel(const float* __restrict__ h,
             const float* __restrict__ iw0, const float* __restrict__ ib0,
             const float* __restrict__ iw1, const float* __restrict__ ib1,
             const float* __restrict__ iw2,
             const float* __restrict__ nw0, const float* __restrict__ nb0,
             const float* __restrict__ nw1, const float* __restrict__ nb1,
             const float* __restrict__ nw2, const float* __restrict__ nb2)
{
    extern __shared__ float sm[];
    float* w_s    = sm + BW_W;
    float* h_s    = sm + BW_H;
    float* base_s = sm + BW_BASE;
    float* w0_s   = sm + BW_W0;
    float* bp_s   = sm + BW_BP;
    int*   mi_s   = (int*)(sm + BW_MI);
    float* iw2_s  = sm + BW_IW2;
    float* a_s    = sm + BW_A1;
    float* a2_s   = sm + BW_A2;
    float* red_s  = sm + BW_RED;

    const int tx = threadIdx.x;
    const int b  = blockIdx.x;
    const int npos  = g_npos;
    const int nposp = g_nposp;

    if (tx < IND - 1) h_s[tx] = h[b * (IND - 1) + tx];
    if (tx < HID) iw2_s[tx] = iw2[tx];
    __syncthreads();

    // stage iw1 with iw2 prefolded (coalesced)
    for (int idx = tx; idx < HID * HID; idx += 256)
        w_s[idx] = iw1[idx] * iw2_s[idx & 127];

    // base/breakpoints (tx<128) | nmlp layer0 (128..255)
    if (tx < HID) {
        float acc = ib0[tx];
        #pragma unroll 7
        for (int d = 0; d < IND - 1; ++d)
            acc = fmaf(h_s[d], iw0[(d + 1) * HID + tx], acc);
        base_s[tx] = acc;
        float w0m = iw0[tx];
        w0_s[tx] = w0m;
        float ss;
        if (w0m != 0.0f) ss = -acc / w0m;
        else ss = (acc > 0.0f) ? __int_as_float(0x7f800000) : __int_as_float(0xff800000);
        bp_s[tx] = ss;
        mi_s[tx] = tx;
    } else {
        int k = tx - 128;
        float acc = nb0[k];
        #pragma unroll 7
        for (int d = 0; d < IND - 1; ++d)
            acc = fmaf(h_s[d], nw0[d * HID + k], acc);
        a_s[k] = fmaxf(acc, 0.0f);
    }
    __syncthreads();
    if (tx < HID) {
        float acc = nb1[tx];
        #pragma unroll 8
        for (int m = 0; m < HID; ++m)
            acc = fmaf(a_s[m], nw1[m * HID + tx], acc);
        a2_s[tx] = fmaxf(acc, 0.0f);
    }
    __syncthreads();
    {
        int o  = tx >> 7;
        int n2 = tx & 127;
        float p = a2_s[n2] * nw2[n2 * 2 + o];
        #pragma unroll
        for (int off = 16; off >= 1; off >>= 1)
            p += __shfl_xor_sync(0xffffffffu, p, off);
        if ((tx & 31) == 0) red_s[tx >> 5] = p;
    }
    __syncthreads();
    if (tx == 0)   g_osc[2 * b]     = nb2[0] + ((red_s[0] + red_s[1]) + (red_s[2] + red_s[3]));
    if (tx == 128) g_osc[2 * b + 1] = nb2[1] + ((red_s[4] + red_s[5]) + (red_s[6] + red_s[7]));
    __syncthreads();

    // bitonic sort of 128 breakpoints (ascending, payload mi)
    for (int kk = 2; kk <= 128; kk <<= 1) {
        for (int j = kk >> 1; j > 0; j >>= 1) {
            if (tx < 128) {
                int ixj = tx ^ j;
                if (ixj > tx) {
                    float a = bp_s[tx], c = bp_s[ixj];
                    bool up = ((tx & kk) == 0);
                    if ((a > c) == up) {
                        bp_s[tx] = c; bp_s[ixj] = a;
                        int t2 = mi_s[tx]; mi_s[tx] = mi_s[ixj]; mi_s[ixj] = t2;
                    }
                }
            }
            __syncthreads();
        }
    }
    if (tx < 128) g_bp[b * HID + tx] = bp_s[tx];

    // builder: prefix vectors A_g, B_g -> global
    {
        int k = tx & 127;
        bool isA = (tx < 128);
        int kp = g_iperm[k];
        float* seg = (isA ? g_A : g_Bv) + (size_t)b * SEGF;
        float r = isA ? 0.0f : ib1[k] * iw2_s[k];
        #pragma unroll 4
        for (int g = 128; g >= 1; --g) {
            seg[g * ST + kp] = r;
            int m = mi_s[g - 1];
            float w0m = w0_s[m];
            float wv = w_s[m * HID + k];
            float coef = isA ? w0m : base_s[m];
            coef = (w0m <= 0.0f) ? coef : 0.0f;
            r = fmaf(coef, wv, r);
        }
        seg[kp] = r;
        r = 0.0f;
        #pragma unroll 4
        for (int g = 0; g < 128; ++g) {
            int m = mi_s[g];
            float w0m = w0_s[m];
            float wv = w_s[m * HID + k];
            float coef = isA ? w0m : base_s[m];
            coef = (w0m > 0.0f) ? coef : 0.0f;
            r = fmaf(coef, wv, r);
            seg[(g + 1) * ST + kp] += r;
        }
    }
    // zero pad slots
    {
        int d = nposp - npos;
        float* Ab = g_A  + (size_t)b * SEGF;
        float* Bb = g_Bv + (size_t)b * SEGF;
        for (int idx = tx; idx < 129 * 8; idx += 256) {
            int g = idx >> 3, e = idx & 7;
            int slot = (e < d) ? (npos + e) : (nposp + (HID - npos) + (e - d));
            Ab[g * ST + slot] = 0.0f;
            Bb[g * ST + slot] = 0.0f;
        }
    }
}

// ===================== quad: static point assignment, deterministic =====================
__global__ void __launch_bounds__(256)
quad_kernel(const float* __restrict__ x, const float* __restrict__ ib2)
{
    __shared__ float bp_s[HID];
    __shared__ float steps_s[S1];
    __shared__ float cc_s[S1];
    __shared__ float red_s[256];

    const int b     = blockIdx.x >> 2;     // CPB = 4
    const int chunk = blockIdx.x & 3;
    const int tx    = threadIdx.x;
    const int np4   = g_nposp >> 2;
    const float ib2v = __ldg(ib2);
    const float xb   = __ldg(&x[b]);
    const float xmax = g_xmax;

    if (tx < HID) bp_s[tx] = g_bp[b * HID + tx];
    if (tx < S1) { steps_s[tx] = g_steps[tx]; cc_s[tx] = g_cc[tx]; }
    __syncthreads();

    const float4* Abase = (const float4*)(g_A  + (size_t)b * SEGF);
    const float4* Bbase = (const float4*)(g_Bv + (size_t)b * SEGF);

    const int pend = min((chunk + 1) * PPC, ROWS);
    float acc = 0.0f;
    for (int p = chunk * PPC + tx; p < pend; p += 256) {
        int i = p / S1, j = p - i * S1;
        float tbi = xb * (steps_s[i] + 1.0f) * 0.5f;
        float rem = xmax - tbi;
        float s = fmaf(rem, (steps_s[j] + 1.0f) * 0.5f, tbi);
        float wt = cc_s[i] * cc_s[j] * rem * 0.5f;
        int g = 0;
        #pragma unroll
        for (int stp = 64; stp >= 1; stp >>= 1) {
            int cand = g + stp;
            if (cand <= 128 && bp_s[cand - 1] < s) g = cand;
        }
        const float4* Ag = Abase + g * NK4;
        const float4* Bg = Bbase + g * NK4;
        float pr0 = 0.0f, pr1 = 0.0f;
        int kq = 0;
        #pragma unroll 4
        for (; kq < np4; ++kq) {
            float4 a = __ldg(Ag + kq), bb = __ldg(Bg + kq);
            pr0 += fmaxf(fmaf(s, a.x, bb.x), 0.0f) + fmaxf(fmaf(s, a.y, bb.y), 0.0f);
            pr1 += fmaxf(fmaf(s, a.z, bb.z), 0.0f) + fmaxf(fmaf(s, a.w, bb.w), 0.0f);
        }
        #pragma unroll 4
        for (; kq < NK4; ++kq) {
            float4 a = __ldg(Ag + kq), bb = __ldg(Bg + kq);
            pr0 += fminf(fmaf(s, a.x, bb.x), 0.0f) + fminf(fmaf(s, a.y, bb.y), 0.0f);
            pr1 += fminf(fmaf(s, a.z, bb.z), 0.0f) + fminf(fmaf(s, a.w, bb.w), 0.0f);
        }
        float z = (pr0 + pr1) + ib2v;
        float f = (z > 0.0f) ? (z + 1.0f) : expf(z);   // elu(z)+1
        acc = fmaf(f, wt, acc);
    }
    red_s[tx] = acc;
    __syncthreads();
    for (int o = 128; o > 0; o >>= 1) {
        if (tx < o) red_s[tx] += red_s[tx + o];
        __syncthreads();
    }
    if (tx == 0) g_part[b * CPB + chunk] = red_s[0];
}

// ===================== finish: tiny deterministic combine =====================
__global__ void finish_kernel(const float* __restrict__ x, float* __restrict__ out) {
    int b = threadIdx.x;
    if (b < BSZ) {
        float sum = 0.0f;
        #pragma unroll
        for (int c = 0; c < CPB; c++) sum += g_part[b * CPB + c];
        float outer = sum * x[b] * 0.5f;
        out[b] = expf(g_osc[2 * b + 1]) * outer + g_osc[2 * b];
    }
}

// ===================== launch =====================
extern "C" void kernel_launch(void* const* d_in, const int* in_sizes, int n_in,
                              void* d_out, int out_size) {
    const float* x   = (const float*)d_in[0];
    const float* h   = (const float*)d_in[1];
    const float* iw0 = (const float*)d_in[2];
    const float* ib0 = (const float*)d_in[3];
    const float* iw1 = (const float*)d_in[4];
    const float* ib1 = (const float*)d_in[5];
    const float* iw2 = (const float*)d_in[6];
    const float* ib2 = (const float*)d_in[7];
    const float* nw0 = (const float*)d_in[8];
    const float* nb0 = (const float*)d_in[9];
    const float* nw1 = (const float*)d_in[10];
    const float* nb1 = (const float*)d_in[11];
    const float* nw2 = (const float*)d_in[12];
    const float* nb2 = (const float*)d_in[13];
    float* out = (float*)d_out;
    (void)in_sizes; (void)n_in; (void)out_size;

    const int bsmem = BW_TOT * (int)sizeof(float);
    cudaFuncSetAttribute(build_kernel,
                         cudaFuncAttributeMaxDynamicSharedMemorySize, bsmem);

    prep_kernel<<<1, 256>>>(x, iw2);
    build_kernel<<<BSZ, 256, bsmem>>>(h, iw0, ib0, iw1, ib1, iw2,
                                      nw0, nb0, nw1, nb1, nw2, nb2);
    quad_kernel<<<BSZ * CPB, 256>>>(x, ib2);
    finish_kernel<<<1, 256>>>(x, out);
}

// round 7
// speedup vs baseline: 1.2580x; 1.2580x over previous
#include <cuda_runtime.h>
#include <math.h>

#define BSZ 256
#define IND 64
#define HID 128
#define NB 50
#define S1 51
#define ROWS (S1 * S1)          // 2601
#define ST 136                  // segment row stride in floats (= 34 float4)
#define NK4 34
#define SEGF (129 * ST)         // 17544 floats per b per array
#define CPB 8                   // quad chunks per batch element
#define PTS ((ROWS + CPB - 1) / CPB)   // 326
#define PR  326                 // points per scatter-warp in build (8 warps)
#define PI_D 3.14159265358979323846

// ---------------- global scratch (static device arrays) ----------------
__device__ float g_steps[S1];
__device__ float g_cc[S1];
__device__ float g_xmax;
__device__ int   g_iperm[HID];
__device__ int   g_npos;
__device__ int   g_nposp;
__device__ __align__(16) float g_A[BSZ * SEGF];    // ~18 MB (L2-resident)
__device__ __align__(16) float g_Bv[BSZ * SEGF];   // ~18 MB
__device__ float4 g_meta[BSZ * ROWS];              // segment-sorted, deterministic
__device__ float g_part[BSZ * CPB];                // per-chunk partials
__device__ float g_osc[BSZ * 2];                   // offset, log-scale per b

// ===================== prep =====================
__global__ void prep_kernel(const float* __restrict__ x, const float* __restrict__ iw2) {
    __shared__ float st_s[S1];
    __shared__ double part[256];
    __shared__ float red[256];
    int tx = threadIdx.x;
    if (tx < S1) {
        double st = cos((double)tx * PI_D / (double)NB);
        st_s[tx] = (float)st;
        g_steps[tx] = (float)st;
    }
    double p = 0.0;
    if (tx < 255) {
        int c = tx / 5, u = tx % 5;
        for (int ie = u; ie < 26; ie += 5) {
            int i = 2 * ie;
            double W = (i == 0) ? 1.0 : 2.0 / (1.0 - (double)i * (double)i);
            double l;
            if (c == 0) l = 0.5;
            else {
                l = cos((double)i * (double)c * PI_D / (double)NB);
                if (c == NB) l *= 0.5;
            }
            p += l * (2.0 / (double)NB) * W;
        }
    }
    part[tx] = p;
    __syncthreads();
    if (tx < S1) {
        double s = 0.0;
        for (int u = 0; u < 5; u++) s += part[tx * 5 + u];
        g_cc[tx] = (float)s;
    }
    float mx = -3.0e38f;
    if (tx < BSZ) {
        float xb = x[tx];
        for (int i = 0; i < S1; i++)
            mx = fmaxf(mx, xb * (st_s[i] + 1.0f) * 0.5f);
    }
    red[tx] = mx;
    __syncthreads();
    for (int o = 128; o > 0; o >>= 1) {
        if (tx < o) red[tx] = fmaxf(red[tx], red[tx + o]);
        __syncthreads();
    }
    if (tx == 0) {
        g_xmax = red[0] + 10.0f;
        int P = 0;
        for (int k = 0; k < HID; k++) if (iw2[k] >= 0.0f) g_iperm[k] = P++;
        g_npos = P;
        int Pp = (P + 3) & ~3;
        g_nposp = Pp;
        int Q = Pp;
        for (int k = 0; k < HID; k++) if (iw2[k] < 0.0f)  g_iperm[k] = Q++;
    }
}

// ===================== build =====================
// dynamic smem layout (floats)
#define BW_W     0                 // 16384: iw1 * iw2[k] prefolded
#define BW_H     16384             // 64
#define BW_BASE  (BW_H + 64)       // 128
#define BW_W0    (BW_BASE + 128)   // 128
#define BW_BP    (BW_W0 + 128)     // 128
#define BW_MI    (BW_BP + 128)     // 128 ints
#define BW_IW2   (BW_MI + 128)     // 128
#define BW_A1    (BW_IW2 + 128)    // 128
#define BW_A2    (BW_A1 + 128)     // 128
#define BW_RED   (BW_A2 + 128)     // 8
#define BW_STEPS (BW_RED + 8)      // 64
#define BW_CC    (BW_STEPS + 64)   // 64
#define BW_CNT2  (BW_CC + 64)      // 8*132 ints
#define BW_WOFF  (BW_CNT2 + 8*132) // 8*132 ints
#define BW_OFFS  (BW_WOFF + 8*132) // 132 ints
#define BW_TOT   (BW_OFFS + 132)   // 19724 floats = 78896 B

__device__ __forceinline__ int seg_of(float s, const float* bp_s) {
    int g = 0;
    #pragma unroll
    for (int stp = 64; stp >= 1; stp >>= 1) {
        int cand = g + stp;
        if (cand <= 128 && bp_s[cand - 1] < s) g = cand;
    }
    return g;
}

__global__ void __launch_bounds__(256, 2)
build_kernel(const float* __restrict__ x,   const float* __restrict__ h,
             const float* __restrict__ iw0, const float* __restrict__ ib0,
             const float* __restrict__ iw1, const float* __restrict__ ib1,
             const float* __restrict__ iw2,
             const float* __restrict__ nw0, const float* __restrict__ nb0,
             const float* __restrict__ nw1, const float* __restrict__ nb1,
             const float* __restrict__ nw2, const float* __restrict__ nb2)
{
    extern __shared__ float sm[];
    float* w_s    = sm + BW_W;
    float* h_s    = sm + BW_H;
    float* base_s = sm + BW_BASE;
    float* w0_s   = sm + BW_W0;
    float* bp_s   = sm + BW_BP;
    int*   mi_s   = (int*)(sm + BW_MI);
    float* iw2_s  = sm + BW_IW2;
    float* a_s    = sm + BW_A1;
    float* a2_s   = sm + BW_A2;
    float* red_s  = sm + BW_RED;
    float* steps_s= sm + BW_STEPS;
    float* cc_s   = sm + BW_CC;
    int*   cnt2   = (int*)(sm + BW_CNT2);
    int*   woff   = (int*)(sm + BW_WOFF);
    int*   offs_s = (int*)(sm + BW_OFFS);

    const int tx = threadIdx.x;
    const int warp = tx >> 5, lane = tx & 31;
    const int b  = blockIdx.x;
    const float xb   = x[b];
    const float xmax = g_xmax;
    const int npos  = g_npos;
    const int nposp = g_nposp;

    if (tx < IND - 1) h_s[tx] = h[b * (IND - 1) + tx];
    if (tx < HID) iw2_s[tx] = iw2[tx];
    if (tx < S1) { steps_s[tx] = g_steps[tx]; cc_s[tx] = g_cc[tx]; }
    for (int i = tx; i < 8 * 132; i += 256) cnt2[i] = 0;
    __syncthreads();

    // stage iw1 with iw2 prefolded (coalesced)
    for (int idx = tx; idx < HID * HID; idx += 256)
        w_s[idx] = iw1[idx] * iw2_s[idx & 127];

    // base/breakpoints (tx<128) | nmlp layer0 (128..255)
    if (tx < HID) {
        float acc = ib0[tx];
        #pragma unroll 7
        for (int d = 0; d < IND - 1; ++d)
            acc = fmaf(h_s[d], iw0[(d + 1) * HID + tx], acc);
        base_s[tx] = acc;
        float w0m = iw0[tx];
        w0_s[tx] = w0m;
        float ss;
        if (w0m != 0.0f) ss = -acc / w0m;
        else ss = (acc > 0.0f) ? __int_as_float(0x7f800000) : __int_as_float(0xff800000);
        bp_s[tx] = ss;
        mi_s[tx] = tx;
    } else {
        int k = tx - 128;
        float acc = nb0[k];
        #pragma unroll 7
        for (int d = 0; d < IND - 1; ++d)
            acc = fmaf(h_s[d], nw0[d * HID + k], acc);
        a_s[k] = fmaxf(acc, 0.0f);
    }
    __syncthreads();
    if (tx < HID) {
        float acc = nb1[tx];
        #pragma unroll 8
        for (int m = 0; m < HID; ++m)
            acc = fmaf(a_s[m], nw1[m * HID + tx], acc);
        a2_s[tx] = fmaxf(acc, 0.0f);
    }
    __syncthreads();
    {
        int o  = tx >> 7;
        int n2 = tx & 127;
        float p = a2_s[n2] * nw2[n2 * 2 + o];
        #pragma unroll
        for (int off = 16; off >= 1; off >>= 1)
            p += __shfl_xor_sync(0xffffffffu, p, off);
        if ((tx & 31) == 0) red_s[tx >> 5] = p;
    }
    __syncthreads();
    if (tx == 0)   g_osc[2 * b]     = nb2[0] + ((red_s[0] + red_s[1]) + (red_s[2] + red_s[3]));
    if (tx == 128) g_osc[2 * b + 1] = nb2[1] + ((red_s[4] + red_s[5]) + (red_s[6] + red_s[7]));
    __syncthreads();

    // bitonic sort of 128 breakpoints (ascending, payload mi)
    for (int kk = 2; kk <= 128; kk <<= 1) {
        for (int j = kk >> 1; j > 0; j >>= 1) {
            if (tx < 128) {
                int ixj = tx ^ j;
                if (ixj > tx) {
                    float a = bp_s[tx], c = bp_s[ixj];
                    bool up = ((tx & kk) == 0);
                    if ((a > c) == up) {
                        bp_s[tx] = c; bp_s[ixj] = a;
                        int t2 = mi_s[tx]; mi_s[tx] = mi_s[ixj]; mi_s[ixj] = t2;
                    }
                }
            }
            __syncthreads();
        }
    }

    // builder: prefix vectors A_g, B_g -> global (sign-permuted, iw2/ib1 folded)
    {
        int k = tx & 127;
        bool isA = (tx < 128);
        int kp = g_iperm[k];
        float* seg = (isA ? g_A : g_Bv) + (size_t)b * SEGF;
        float r = isA ? 0.0f : ib1[k] * iw2_s[k];
        #pragma unroll 4
        for (int g = 128; g >= 1; --g) {
            seg[g * ST + kp] = r;
            int m = mi_s[g - 1];
            float w0m = w0_s[m];
            float wv = w_s[m * HID + k];
            float coef = isA ? w0m : base_s[m];
            coef = (w0m <= 0.0f) ? coef : 0.0f;
            r = fmaf(coef, wv, r);
        }
        seg[kp] = r;
        r = 0.0f;
        #pragma unroll 4
        for (int g = 0; g < 128; ++g) {
            int m = mi_s[g];
            float w0m = w0_s[m];
            float wv = w_s[m * HID + k];
            float coef = isA ? w0m : base_s[m];
            coef = (w0m > 0.0f) ? coef : 0.0f;
            r = fmaf(coef, wv, r);
            seg[(g + 1) * ST + kp] += r;
        }
    }
    // zero pad slots
    {
        int d = nposp - npos;
        float* Ab = g_A  + (size_t)b * SEGF;
        float* Bb = g_Bv + (size_t)b * SEGF;
        for (int idx = tx; idx < 129 * 8; idx += 256) {
            int g = idx >> 3, e = idx & 7;
            int slot = (e < d) ? (npos + e) : (nposp + (HID - npos) + (e - d));
            Ab[g * ST + slot] = 0.0f;
            Bb[g * ST + slot] = 0.0f;
        }
    }

    // ---- deterministic counting sort of points by segment ----
    // phase 1: per-warp histogram over disjoint p ranges
    {
        int p0 = warp * PR;
        int pend = min(p0 + PR, ROWS);
        for (int p = p0 + lane; p < pend; p += 32) {
            int i = p / S1, j = p - i * S1;
            float tbi = xb * (steps_s[i] + 1.0f) * 0.5f;
            float rem = xmax - tbi;
            float s = fmaf(rem, (steps_s[j] + 1.0f) * 0.5f, tbi);
            int g = seg_of(s, bp_s);
            atomicAdd(&cnt2[warp * 132 + g], 1);
        }
    }
    __syncthreads();
    // phase 2: prefix sums -> global offs + per-warp offs
    if (tx < 129) {
        int t = 0;
        #pragma unroll
        for (int w = 0; w < 8; w++) t += cnt2[w * 132 + tx];
        offs_s[tx] = t;
    }
    __syncthreads();
    if (tx == 0) {
        int run = 0;
        for (int g = 0; g <= 128; ++g) { int t = offs_s[g]; offs_s[g] = run; run += t; }
    }
    __syncthreads();
    if (tx < 129) {
        int run = offs_s[tx];
        #pragma unroll
        for (int w = 0; w < 8; w++) { woff[w * 132 + tx] = run; run += cnt2[w * 132 + tx]; }
    }
    __syncthreads();
    // phase 3: each warp scatters its range; rank via match_any (deterministic)
    {
        int* myoff = woff + warp * 132;
        int p0 = warp * PR;
        int pend = min(p0 + PR, ROWS);
        for (int base = p0; base < pend; base += 32) {
            int p = base + lane;
            bool valid = (p < pend);
            float s = 0.0f, wt = 0.0f;
            int g;
            if (valid) {
                int i = p / S1, j = p - i * S1;
                float tbi = xb * (steps_s[i] + 1.0f) * 0.5f;
                float rem = xmax - tbi;
                s = fmaf(rem, (steps_s[j] + 1.0f) * 0.5f, tbi);
                wt = cc_s[i] * cc_s[j] * rem * 0.5f;
                g = seg_of(s, bp_s);
            } else {
                g = 512 + lane;   // distinct dummy, never collides with real g
            }
            unsigned mm = __match_any_sync(0xffffffffu, g);
            int rank_in = __popc(mm & ((1u << lane) - 1u));
            int leader = __ffs(mm) - 1;
            int boff = 0;
            if (lane == leader && valid) {
                boff = myoff[g];
                myoff[g] = boff + __popc(mm);
            }
            boff = __shfl_sync(0xffffffffu, boff, leader);
            if (valid)
                g_meta[b * ROWS + boff + rank_in] =
                    make_float4(s, wt, __int_as_float(g), 0.0f);
        }
    }
}

// ===================== quad: sorted order, direct deterministic partials =====================
__global__ void __launch_bounds__(128)
quad_kernel(const float* __restrict__ ib2)
{
    __shared__ float red_s[128];
    const int b     = blockIdx.x >> 3;     // CPB = 8
    const int chunk = blockIdx.x & 7;
    const int tx    = threadIdx.x;
    const int np4   = g_nposp >> 2;
    const float ib2v = __ldg(ib2);

    const float4* Abase = (const float4*)(g_A  + (size_t)b * SEGF);
    const float4* Bbase = (const float4*)(g_Bv + (size_t)b * SEGF);

    const int q0   = chunk * PTS;
    const int qend = min(q0 + PTS, ROWS);
    float acc = 0.0f;
    for (int q = q0 + tx; q < qend; q += 128) {
        float4 m = __ldg(&g_meta[b * ROWS + q]);
        int g = __float_as_int(m.z);
        const float4* Ag = Abase + g * NK4;
        const float4* Bg = Bbase + g * NK4;
        float s = m.x;
        float pr0 = 0.0f, pr1 = 0.0f;
        int kq = 0;
        #pragma unroll 4
        for (; kq < np4; ++kq) {
            float4 a = __ldg(Ag + kq), bb = __ldg(Bg + kq);
            pr0 += fmaxf(fmaf(s, a.x, bb.x), 0.0f) + fmaxf(fmaf(s, a.y, bb.y), 0.0f);
            pr1 += fmaxf(fmaf(s, a.z, bb.z), 0.0f) + fmaxf(fmaf(s, a.w, bb.w), 0.0f);
        }
        #pragma unroll 4
        for (; kq < NK4; ++kq) {
            float4 a = __ldg(Ag + kq), bb = __ldg(Bg + kq);
            pr0 += fminf(fmaf(s, a.x, bb.x), 0.0f) + fminf(fmaf(s, a.y, bb.y), 0.0f);
            pr1 += fminf(fmaf(s, a.z, bb.z), 0.0f) + fminf(fmaf(s, a.w, bb.w), 0.0f);
        }
        float z = (pr0 + pr1) + ib2v;
        float f = (z > 0.0f) ? (z + 1.0f) : expf(z);   // elu(z)+1
        acc = fmaf(f, m.y, acc);
    }
    red_s[tx] = acc;
    __syncthreads();
    for (int o = 64; o > 0; o >>= 1) {
        if (tx < o) red_s[tx] += red_s[tx + o];
        __syncthreads();
    }
    if (tx == 0) g_part[b * CPB + chunk] = red_s[0];
}

// ===================== finish: tiny deterministic combine =====================
__global__ void finish_kernel(const float* __restrict__ x, float* __restrict__ out) {
    int b = threadIdx.x;
    if (b < BSZ) {
        float sum = 0.0f;
        #pragma unroll
        for (int c = 0; c < CPB; c++) sum += g_part[b * CPB + c];
        float outer = sum * x[b] * 0.5f;
        out[b] = expf(g_osc[2 * b + 1]) * outer + g_osc[2 * b];
    }
}

// ===================== launch =====================
extern "C" void kernel_launch(void* const* d_in, const int* in_sizes, int n_in,
                              void* d_out, int out_size) {
    const float* x   = (const float*)d_in[0];
    const float* h   = (const float*)d_in[1];
    const float* iw0 = (const float*)d_in[2];
    const float* ib0 = (const float*)d_in[3];
    const float* iw1 = (const float*)d_in[4];
    const float* ib1 = (const float*)d_in[5];
    const float* iw2 = (const float*)d_in[6];
    const float* ib2 = (const float*)d_in[7];
    const float* nw0 = (const float*)d_in[8];
    const float* nb0 = (const float*)d_in[9];
    const float* nw1 = (const float*)d_in[10];
    const float* nb1 = (const float*)d_in[11];
    const float* nw2 = (const float*)d_in[12];
    const float* nb2 = (const float*)d_in[13];
    float* out = (float*)d_out;
    (void)in_sizes; (void)n_in; (void)out_size;

    const int bsmem = BW_TOT * (int)sizeof(float);
    cudaFuncSetAttribute(build_kernel,
                         cudaFuncAttributeMaxDynamicSharedMemorySize, bsmem);

    prep_kernel<<<1, 256>>>(x, iw2);
    build_kernel<<<BSZ, 256, bsmem>>>(x, h, iw0, ib0, iw1, ib1, iw2,
                                      nw0, nb0, nw1, nb1, nw2, nb2);
    quad_kernel<<<BSZ * CPB, 128>>>(ib2);
    finish_kernel<<<1, 256>>>(x, out);
}

// round 9
// speedup vs baseline: 1.2738x; 1.0126x over previous
#include <cuda_runtime.h>
#include <math.h>

#define BSZ 256
#define IND 64
#define HID 128
#define NB 50
#define S1 51
#define ROWS (S1 * S1)            // 2601
#define SEGROW 272                // interleaved A/B row: 34 * (A4 + B4) floats
#define NK4 34
#define SEGB (129 * SEGROW)       // 35088 floats per b
#define CPB 8
#define PTS ((ROWS + CPB - 1) / CPB)   // 326
#define PR  326                   // points per scatter-warp in build
#define PI_D 3.14159265358979323846

// ---------------- global scratch ----------------
__device__ float g_steps[S1];
__device__ float g_cc[S1];
__device__ float g_xmax;
__device__ int   g_iperm[HID];    // logical k -> physical slot (0..130)
__device__ int   g_npos;
__device__ int   g_nposp;
__device__ __align__(16) float g_AB[BSZ * SEGB];   // ~36 MB interleaved A/B
__device__ float4 g_meta[BSZ * ROWS];
__device__ float g_part[BSZ * CPB];
__device__ float g_osc[BSZ * 2];
__device__ int   g_done[BSZ];

// ===================== prep =====================
__global__ void prep_kernel(const float* __restrict__ x, const float* __restrict__ iw2) {
    __shared__ float st_s[S1];
    __shared__ double part[256];
    __shared__ float red[256];
    int tx = threadIdx.x;
    if (tx < BSZ) g_done[tx] = 0;
    if (tx < S1) {
        double st = cos((double)tx * PI_D / (double)NB);
        st_s[tx] = (float)st;
        g_steps[tx] = (float)st;
    }
    double p = 0.0;
    if (tx < 255) {
        int c = tx / 5, u = tx % 5;
        for (int ie = u; ie < 26; ie += 5) {
            int i = 2 * ie;
            double W = (i == 0) ? 1.0 : 2.0 / (1.0 - (double)i * (double)i);
            double l;
            if (c == 0) l = 0.5;
            else {
                l = cos((double)i * (double)c * PI_D / (double)NB);
                if (c == NB) l *= 0.5;
            }
            p += l * (2.0 / (double)NB) * W;
        }
    }
    part[tx] = p;
    __syncthreads();
    if (tx < S1) {
        double s = 0.0;
        for (int u = 0; u < 5; u++) s += part[tx * 5 + u];
        g_cc[tx] = (float)s;
    }
    float mx = -3.0e38f;
    if (tx < BSZ) {
        float xb = x[tx];
        for (int i = 0; i < S1; i++)
            mx = fmaxf(mx, xb * (st_s[i] + 1.0f) * 0.5f);
    }
    red[tx] = mx;
    __syncthreads();
    for (int o = 128; o > 0; o >>= 1) {
        if (tx < o) red[tx] = fmaxf(red[tx], red[tx + o]);
        __syncthreads();
    }
    if (tx == 0) {
        g_xmax = red[0] + 10.0f;
        int P = 0;
        for (int k = 0; k < HID; k++) if (iw2[k] >= 0.0f) g_iperm[k] = P++;
        g_npos = P;
        int Pp = (P + 3) & ~3;
        g_nposp = Pp;
        int Q = Pp;
        for (int k = 0; k < HID; k++) if (iw2[k] < 0.0f)  g_iperm[k] = Q++;
    }
}

// ===================== build =====================
// smem layout (floats)
#define BW_W     0                 // 16384: w[m][k] = iw1[m][k]*iw2[k] (logical)
#define BW_H     16384             // 64
#define BW_BASE  (BW_H + 64)       // 128
#define BW_W0    (BW_BASE + 128)   // 128
#define BW_BP    (BW_W0 + 128)     // 128
#define BW_MI    (BW_BP + 128)     // 128 ints
#define BW_IW2   (BW_MI + 128)     // 128
#define BW_A1    (BW_IW2 + 128)    // 128
#define BW_A2    (BW_A1 + 128)     // 128
#define BW_RED   (BW_A2 + 128)     // 8
#define BW_STEPS (BW_RED + 8)      // 64
#define BW_CC    (BW_STEPS + 64)   // 64
#define BW_CNT2  (BW_CC + 64)      // 8*132 ints
#define BW_WOFF  (BW_CNT2 + 8*132) // 8*132 ints
#define BW_OFFS  (BW_WOFF + 8*132) // 132 ints
#define BW_TOT   (BW_OFFS + 132)   // 19852 floats = 79408 B

__device__ __forceinline__ int seg_of(float s, const float* bp_s) {
    int g = 0;
    #pragma unroll
    for (int stp = 64; stp >= 1; stp >>= 1) {
        int cand = g + stp;
        if (cand <= 128 && bp_s[cand - 1] < s) g = cand;
    }
    return g;
}

__global__ void __launch_bounds__(256, 2)
build_kernel(const float* __restrict__ x,   const float* __restrict__ h,
             const float* __restrict__ iw0, const float* __restrict__ ib0,
             const float* __restrict__ iw1, const float* __restrict__ ib1,
             const float* __restrict__ iw2,
             const float* __restrict__ nw0, const float* __restrict__ nb0,
             const float* __restrict__ nw1, const float* __restrict__ nb1,
             const float* __restrict__ nw2, const float* __restrict__ nb2)
{
    extern __shared__ float sm[];
    float* w_s    = sm + BW_W;
    float* h_s    = sm + BW_H;
    float* base_s = sm + BW_BASE;
    float* w0_s   = sm + BW_W0;
    float* bp_s   = sm + BW_BP;
    int*   mi_s   = (int*)(sm + BW_MI);
    float* iw2_s  = sm + BW_IW2;
    float* a_s    = sm + BW_A1;
    float* a2_s   = sm + BW_A2;
    float* red_s  = sm + BW_RED;
    float* steps_s= sm + BW_STEPS;
    float* cc_s   = sm + BW_CC;
    int*   cnt2   = (int*)(sm + BW_CNT2);
    int*   woff   = (int*)(sm + BW_WOFF);
    int*   offs_s = (int*)(sm + BW_OFFS);

    const int tx = threadIdx.x;
    const int warp = tx >> 5, lane = tx & 31;
    const int b  = blockIdx.x;
    const float xb   = x[b];
    const float xmax = g_xmax;
    const int npos  = g_npos;
    const int nposp = g_nposp;

    if (tx < IND - 1) h_s[tx] = h[b * (IND - 1) + tx];
    if (tx < HID) iw2_s[tx] = iw2[tx];
    if (tx < S1) { steps_s[tx] = g_steps[tx]; cc_s[tx] = g_cc[tx]; }
    for (int i = tx; i < 8 * 132; i += 256) cnt2[i] = 0;
    __syncthreads();

    // stage iw1 with iw2 prefolded (logical columns, coalesced)
    for (int idx = tx; idx < HID * HID; idx += 256)
        w_s[idx] = iw1[idx] * iw2_s[idx & 127];

    // base/breakpoints (tx<128) | nmlp layer0 (128..255)
    if (tx < HID) {
        float acc = ib0[tx];
        #pragma unroll 7
        for (int d = 0; d < IND - 1; ++d)
            acc = fmaf(h_s[d], iw0[(d + 1) * HID + tx], acc);
        base_s[tx] = acc;
        float w0m = iw0[tx];
        w0_s[tx] = w0m;
        float ss;
        if (w0m != 0.0f) ss = -acc / w0m;
        else ss = (acc > 0.0f) ? __int_as_float(0x7f800000) : __int_as_float(0xff800000);
        bp_s[tx] = ss;
        mi_s[tx] = tx;
    } else {
        int k = tx - 128;
        float acc = nb0[k];
        #pragma unroll 7
        for (int d = 0; d < IND - 1; ++d)
            acc = fmaf(h_s[d], nw0[d * HID + k], acc);
        a_s[k] = fmaxf(acc, 0.0f);
    }
    __syncthreads();
    if (tx < HID) {
        float acc = nb1[tx];
        #pragma unroll 8
        for (int m = 0; m < HID; ++m)
            acc = fmaf(a_s[m], nw1[m * HID + tx], acc);
        a2_s[tx] = fmaxf(acc, 0.0f);
    }
    __syncthreads();
    {
        int o  = tx >> 7;
        int n2 = tx & 127;
        float p = a2_s[n2] * nw2[n2 * 2 + o];
        #pragma unroll
        for (int off = 16; off >= 1; off >>= 1)
            p += __shfl_xor_sync(0xffffffffu, p, off);
        if ((tx & 31) == 0) red_s[tx >> 5] = p;
    }
    __syncthreads();
    if (tx == 0)   g_osc[2 * b]     = nb2[0] + ((red_s[0] + red_s[1]) + (red_s[2] + red_s[3]));
    if (tx == 128) g_osc[2 * b + 1] = nb2[1] + ((red_s[4] + red_s[5]) + (red_s[6] + red_s[7]));
    __syncthreads();

    // bitonic sort of 128 breakpoints (ascending, payload mi)
    for (int kk = 2; kk <= 128; kk <<= 1) {
        for (int j = kk >> 1; j > 0; j >>= 1) {
            if (tx < 128) {
                int ixj = tx ^ j;
                if (ixj > tx) {
                    float a = bp_s[tx], c = bp_s[ixj];
                    bool up = ((tx & kk) == 0);
                    if ((a > c) == up) {
                        bp_s[tx] = c; bp_s[ixj] = a;
                        int t2 = mi_s[tx]; mi_s[tx] = mi_s[ixj]; mi_s[ixj] = t2;
                    }
                }
            }
            __syncthreads();
        }
    }

    // ---- single-pass builder: stores only (no global RMW chain) ----
    {
        const int k = tx & 127;              // logical hidden column
        const bool isA = (tx < 128);
        const int kp = g_iperm[k];           // physical slot (0..130)
        float* segb = g_AB + (size_t)b * SEGB;
        const int fidx = ((kp >> 2) << 3) + (kp & 3) + (isA ? 0 : 4);
        // init segment 0: all w0<=0 units active
        float r = isA ? 0.0f : ib1[k] * iw2_s[k];
        #pragma unroll 8
        for (int m = 0; m < HID; ++m) {
            float w0m = w0_s[m];
            float coef = isA ? w0m : base_s[m];
            coef = (w0m <= 0.0f) ? coef : 0.0f;
            r = fmaf(coef, w_s[(m << 7) + k], r);
        }
        segb[fidx] = r;
        // forward: crossing sorted breakpoint g -> unit mi[g] enters (w0>0) or leaves (w0<=0)
        #pragma unroll 8
        for (int g = 0; g < 128; ++g) {
            int m = mi_s[g];
            float w0m = w0_s[m];
            float coef = isA ? w0m : base_s[m];
            float csel = (w0m > 0.0f) ? coef : -coef;
            r = fmaf(csel, w_s[(m << 7) + k], r);
            segb[(g + 1) * SEGROW + fidx] = r;
        }
    }
    // zero pad slots (8 per row: gap npos..nposp-1 and tail)
    {
        int d = nposp - npos;
        float* segb = g_AB + (size_t)b * SEGB;
        for (int idx = tx; idx < 129 * 8; idx += 256) {
            int g = idx >> 3, e = idx & 7;
            int sl = (e < d) ? (npos + e) : (nposp + (HID - npos) + (e - d));
            int fa = g * SEGROW + ((sl >> 2) << 3) + (sl & 3);
            segb[fa] = 0.0f;
            segb[fa + 4] = 0.0f;
        }
    }

    // ---- deterministic counting sort of points by segment ----
    {
        int p0 = warp * PR;
        int pend = min(p0 + PR, ROWS);
        for (int p = p0 + lane; p < pend; p += 32) {
            int i = p / S1, j = p - i * S1;
            float tbi = xb * (steps_s[i] + 1.0f) * 0.5f;
            float rem = xmax - tbi;
            float s = fmaf(rem, (steps_s[j] + 1.0f) * 0.5f, tbi);
            atomicAdd(&cnt2[warp * 132 + seg_of(s, bp_s)], 1);
        }
    }
    __syncthreads();
    if (tx < 129) {
        int t = 0;
        #pragma unroll
        for (int w = 0; w < 8; w++) t += cnt2[w * 132 + tx];
        offs_s[tx] = t;
    }
    __syncthreads();
    if (tx == 0) {
        int run = 0;
        for (int g = 0; g <= 128; ++g) { int t = offs_s[g]; offs_s[g] = run; run += t; }
    }
    __syncthreads();
    if (tx < 129) {
        int run = offs_s[tx];
        #pragma unroll
        for (int w = 0; w < 8; w++) { woff[w * 132 + tx] = run; run += cnt2[w * 132 + tx]; }
    }
    __syncthreads();
    {
        int* myoff = woff + warp * 132;
        int p0 = warp * PR;
        int pend = min(p0 + PR, ROWS);
        for (int base = p0; base < pend; base += 32) {
            int p = base + lane;
            bool valid = (p < pend);
            float s = 0.0f, wt = 0.0f;
            int g;
            if (valid) {
                int i = p / S1, j = p - i * S1;
                float tbi = xb * (steps_s[i] + 1.0f) * 0.5f;
                float rem = xmax - tbi;
                s = fmaf(rem, (steps_s[j] + 1.0f) * 0.5f, tbi);
                wt = cc_s[i] * cc_s[j] * rem * 0.5f;
                g = seg_of(s, bp_s);
            } else {
                g = 512 + lane;   // distinct dummies
            }
            unsigned mm = __match_any_sync(0xffffffffu, g);
            int rank_in = __popc(mm & ((1u << lane) - 1u));
            int leader = __ffs(mm) - 1;
            int boff = 0;
            if (lane == leader && valid) {
                boff = myoff[g];
                myoff[g] = boff + __popc(mm);
            }
            boff = __shfl_sync(0xffffffffu, boff, leader);
            if (valid)
                g_meta[b * ROWS + boff + rank_in] =
                    make_float4(s, wt, __int_as_float(g), 0.0f);
        }
    }
}

// ===================== quad (+ fused final combine) =====================
__global__ void __launch_bounds__(128)
quad_kernel(const float* __restrict__ x, const float* __restrict__ ib2,
            float* __restrict__ out)
{
    __shared__ float red_s[128];
    const int b     = blockIdx.x >> 3;     // CPB = 8
    const int chunk = blockIdx.x & 7;
    const int tx    = threadIdx.x;
    const int np4   = g_nposp >> 2;
    const float ib2v = __ldg(ib2);

    const float4* ABb = (const float4*)(g_AB + (size_t)b * SEGB);

    const int q0   = chunk * PTS;
    const int qend = min(q0 + PTS, ROWS);
    float acc = 0.0f;
    for (int q = q0 + tx; q < qend; q += 128) {
        float4 m = __ldg(&g_meta[b * ROWS + q]);
        const float4* row = ABb + __float_as_int(m.z) * (SEGROW / 4);
        float s = m.x;
        float pr0 = 0.0f, pr1 = 0.0f;
        int kq = 0;
        #pragma unroll 4
        for (; kq < np4; ++kq) {
            float4 a = __ldg(row + 2 * kq), bb = __ldg(row + 2 * kq + 1);
            pr0 += fmaxf(fmaf(s, a.x, bb.x), 0.0f) + fmaxf(fmaf(s, a.y, bb.y), 0.0f);
            pr1 += fmaxf(fmaf(s, a.z, bb.z), 0.0f) + fmaxf(fmaf(s, a.w, bb.w), 0.0f);
        }
        #pragma unroll 4
        for (; kq < NK4; ++kq) {
            float4 a = __ldg(row + 2 * kq), bb = __ldg(row + 2 * kq + 1);
            pr0 += fminf(fmaf(s, a.x, bb.x), 0.0f) + fminf(fmaf(s, a.y, bb.y), 0.0f);
            pr1 += fminf(fmaf(s, a.z, bb.z), 0.0f) + fminf(fmaf(s, a.w, bb.w), 0.0f);
        }
        float z = (pr0 + pr1) + ib2v;
        float f = (z > 0.0f) ? (z + 1.0f) : expf(z);   // elu(z)+1
        acc = fmaf(f, m.y, acc);
    }
    red_s[tx] = acc;
    __syncthreads();
    for (int o = 64; o > 0; o >>= 1) {
        if (tx < o) red_s[tx] += red_s[tx + o];
        __syncthreads();
    }
    if (tx == 0) {
        g_part[b * CPB + chunk] = red_s[0];
        __threadfence();
        int old = atomicAdd(&g_done[b], 1);
        if (old == CPB - 1) {
            __threadfence();
            float sum = 0.0f;
            #pragma unroll
            for (int c = 0; c < CPB; c++) sum += __ldcg(&g_part[b * CPB + c]);
            float outer = sum * __ldg(&x[b]) * 0.5f;
            out[b] = expf(__ldcg(&g_osc[2 * b + 1])) * outer + __ldcg(&g_osc[2 * b]);
        }
    }
}

// ===================== launch =====================
extern "C" void kernel_launch(void* const* d_in, const int* in_sizes, int n_in,
                              void* d_out, int out_size) {
    const float* x   = (const float*)d_in[0];
    const float* h   = (const float*)d_in[1];
    const float* iw0 = (const float*)d_in[2];
    const float* ib0 = (const float*)d_in[3];
    const float* iw1 = (const float*)d_in[4];
    const float* ib1 = (const float*)d_in[5];
    const float* iw2 = (const float*)d_in[6];
    const float* ib2 = (const float*)d_in[7];
    const float* nw0 = (const float*)d_in[8];
    const float* nb0 = (const float*)d_in[9];
    const float* nw1 = (const float*)d_in[10];
    const float* nb1 = (const float*)d_in[11];
    const float* nw2 = (const float*)d_in[12];
    const float* nb2 = (const float*)d_in[13];
    float* out = (float*)d_out;
    (void)in_sizes; (void)n_in; (void)out_size;

    const int bsmem = BW_TOT * (int)sizeof(float);
    cudaFuncSetAttribute(build_kernel,
                         cudaFuncAttributeMaxDynamicSharedMemorySize, bsmem);

    prep_kernel<<<1, 256>>>(x, iw2);
    build_kernel<<<BSZ, 256, bsmem>>>(x, h, iw0, ib0, iw1, ib1, iw2,
                                      nw0, nb0, nw1, nb1, nw2, nb2);
    quad_kernel<<<BSZ * CPB, 128>>>(x, ib2, out);
}

// round 10
// speedup vs baseline: 1.3871x; 1.0889x over previous
#include <cuda_runtime.h>
#include <math.h>

#define BSZ 256
#define IND 64
#define HID 128
#define NB 50
#define S1 51
#define ROWS (S1 * S1)            // 2601
#define SEGROW 272                // interleaved A/B row: 34 * (A4 + B4) floats
#define NK4 34
#define SEGB (129 * SEGROW)       // 35088 floats per b
#define CPB 8
#define PTS ((ROWS + CPB - 1) / CPB)   // 326
#define PR  326                   // points per scatter-warp in build
#define TH0 0.06283185307179586f  // pi/50

// ---------------- global scratch ----------------
__device__ int   g_nposp;
__device__ __align__(16) float g_AB[BSZ * SEGB];   // ~36 MB interleaved A/B
__device__ float4 g_meta[BSZ * ROWS];
__device__ float g_part[BSZ * CPB];
__device__ float g_osc[BSZ * 2];
__device__ int   g_done[BSZ];

__device__ __forceinline__ int seg_of(float s, const float* bp_s) {
    int g = 0;
    #pragma unroll
    for (int stp = 64; stp >= 1; stp >>= 1) {
        int cand = g + stp;
        if (cand <= 128 && bp_s[cand - 1] < s) g = cand;
    }
    return g;
}

// ===================== build: fully self-contained per-b setup =====================
__global__ void __launch_bounds__(256, 3)
build_kernel(const float* __restrict__ x,   const float* __restrict__ h,
             const float* __restrict__ iw0, const float* __restrict__ ib0,
             const float* __restrict__ iw1, const float* __restrict__ ib1,
             const float* __restrict__ iw2,
             const float* __restrict__ nw0, const float* __restrict__ nb0,
             const float* __restrict__ nw1, const float* __restrict__ nb1,
             const float* __restrict__ nw2, const float* __restrict__ nb2)
{
    __shared__ float h_s[64];
    __shared__ float base_s[HID];
    __shared__ float w0_s[HID];
    __shared__ float bp_s[HID];
    __shared__ int   mi_s[HID];
    __shared__ float iw2_s[HID];
    __shared__ int   iperm_s[HID];
    __shared__ float a_s[HID];
    __shared__ float a2_s[HID];
    __shared__ float red_s[8];
    __shared__ float steps_s[S1 + 1];
    __shared__ float cc_s[S1 + 1];
    __shared__ float redx_s[256];
    __shared__ int   cnt2[8 * 132];
    __shared__ int   woff[8 * 132];
    __shared__ int   offs_s[132];
    __shared__ int   wc_s[4];
    __shared__ int   npos_s, nposp_s;
    __shared__ float xmax_s;

    const int tx = threadIdx.x;
    const int warp = tx >> 5, lane = tx & 31;
    const int b  = blockIdx.x;
    const float xb = x[b];

    // ---- stage small vectors + zero histograms ----
    if (tx < IND - 1) h_s[tx] = h[b * (IND - 1) + tx];
    if (tx < HID) iw2_s[tx] = iw2[tx];
    for (int i = tx; i < 8 * 132; i += 256) cnt2[i] = 0;
    if (tx == 0) g_done[b] = 0;

    // ---- xmax: max over all b of x_b*(u in [0,1]) -> max(max_b x, 0) + 10 ----
    redx_s[tx] = x[tx];           // BSZ == 256 == blockDim
    __syncthreads();
    for (int o = 128; o > 0; o >>= 1) {
        if (tx < o) redx_s[tx] = fmaxf(redx_s[tx], redx_s[tx + o]);
        __syncthreads();
    }
    if (tx == 0) xmax_s = fmaxf(redx_s[0], 0.0f) + 10.0f;

    // ---- steps + cc (float recurrences; enter result smoothly) ----
    if (tx < S1) steps_s[tx] = cosf((float)tx * TH0);
    __syncthreads();
    if (tx < S1) {
        float sv = steps_s[tx];
        float c1 = fmaf(2.0f * sv, sv, -1.0f);    // cos(2*c*th0)
        float cm2 = 1.0f, cm1 = c1;
        float sum = 1.0f;                          // ie=0 term, W=1
        #pragma unroll
        for (int ie = 1; ie <= 25; ++ie) {
            float cv = (ie == 1) ? c1 : fmaf(2.0f * c1, cm1, -cm2);
            if (ie > 1) { cm2 = cm1; cm1 = cv; }
            float W = 2.0f / (1.0f - 4.0f * (float)(ie * ie));
            sum = fmaf(cv, W, sum);
        }
        float v = sum * (2.0f / (float)NB);
        if (tx == 0 || tx == NB) v *= 0.5f;
        cc_s[tx] = v;
    }

    // ---- iperm via ballot scan ----
    {
        bool pos = false; unsigned bal = 0;
        if (tx < HID) {
            pos = (iw2_s[tx] >= 0.0f);
            bal = __ballot_sync(0xffffffffu, pos);
            if (lane == 0) wc_s[warp] = __popc(bal);
        }
        __syncthreads();
        if (tx == 0) {
            int np = wc_s[0] + wc_s[1] + wc_s[2] + wc_s[3];
            npos_s = np;
            nposp_s = (np + 3) & ~3;
            if (b == 0) g_nposp = nposp_s;
        }
        __syncthreads();
        if (tx < HID) {
            unsigned lt = (1u << lane) - 1u;
            int posbef = __popc(bal & lt);
            int prefpos = 0;
            #pragma unroll
            for (int wi = 0; wi < 4; ++wi) if (wi < warp) prefpos += wc_s[wi];
            int slot;
            if (pos) slot = prefpos + posbef;
            else     slot = nposp_s + (warp * 32 - prefpos) + (lane - posbef);
            iperm_s[tx] = slot;
        }
    }

    const float xmax = xmax_s;
    const int npos  = npos_s;
    const int nposp = nposp_s;

    // ---- base/breakpoints (tx<128) | nmlp layer0 (128..255) ----
    if (tx < HID) {
        float acc = ib0[tx];
        #pragma unroll 7
        for (int d = 0; d < IND - 1; ++d)
            acc = fmaf(h_s[d], iw0[(d + 1) * HID + tx], acc);
        base_s[tx] = acc;
        float w0m = iw0[tx];
        w0_s[tx] = w0m;
        float ss;
        if (w0m != 0.0f) ss = -acc / w0m;
        else ss = (acc > 0.0f) ? __int_as_float(0x7f800000) : __int_as_float(0xff800000);
        bp_s[tx] = ss;
        mi_s[tx] = tx;
    } else {
        int k = tx - 128;
        float acc = nb0[k];
        #pragma unroll 7
        for (int d = 0; d < IND - 1; ++d)
            acc = fmaf(h_s[d], nw0[d * HID + k], acc);
        a_s[k] = fmaxf(acc, 0.0f);
    }
    __syncthreads();
    if (tx < HID) {
        float acc = nb1[tx];
        #pragma unroll 8
        for (int m = 0; m < HID; ++m)
            acc = fmaf(a_s[m], nw1[m * HID + tx], acc);
        a2_s[tx] = fmaxf(acc, 0.0f);
    }
    __syncthreads();
    {
        int o  = tx >> 7;
        int n2 = tx & 127;
        float p = a2_s[n2] * nw2[n2 * 2 + o];
        #pragma unroll
        for (int off = 16; off >= 1; off >>= 1)
            p += __shfl_xor_sync(0xffffffffu, p, off);
        if (lane == 0) red_s[warp] = p;
    }
    __syncthreads();
    if (tx == 0)   g_osc[2 * b]     = nb2[0] + ((red_s[0] + red_s[1]) + (red_s[2] + red_s[3]));
    if (tx == 128) g_osc[2 * b + 1] = nb2[1] + ((red_s[4] + red_s[5]) + (red_s[6] + red_s[7]));
    __syncthreads();

    // ---- bitonic sort of 128 breakpoints (ascending, payload mi) ----
    for (int kk = 2; kk <= 128; kk <<= 1) {
        for (int j = kk >> 1; j > 0; j >>= 1) {
            if (tx < 128) {
                int ixj = tx ^ j;
                if (ixj > tx) {
                    float a = bp_s[tx], c = bp_s[ixj];
                    bool up = ((tx & kk) == 0);
                    if ((a > c) == up) {
                        bp_s[tx] = c; bp_s[ixj] = a;
                        int t2 = mi_s[tx]; mi_s[tx] = mi_s[ixj]; mi_s[ixj] = t2;
                    }
                }
            }
            __syncthreads();
        }
    }

    // ---- single-pass builder: iw1 from L2, iw2 factored to the store ----
    {
        const int k = tx & 127;
        const bool isA = (tx < 128);
        const int kp = iperm_s[k];
        const float w2k = iw2_s[k];
        float* segb = g_AB + (size_t)b * SEGB;
        const int fidx = ((kp >> 2) << 3) + (kp & 3) + (isA ? 0 : 4);
        float r = isA ? 0.0f : ib1[k];
        #pragma unroll 8
        for (int m = 0; m < HID; ++m) {
            float w0m = w0_s[m];
            float coef = isA ? w0m : base_s[m];
            coef = (w0m <= 0.0f) ? coef : 0.0f;
            r = fmaf(coef, __ldg(&iw1[(m << 7) + k]), r);
        }
        segb[fidx] = r * w2k;
        #pragma unroll 8
        for (int g = 0; g < 128; ++g) {
            int m = mi_s[g];
            float w0m = w0_s[m];
            float coef = isA ? w0m : base_s[m];
            float csel = (w0m > 0.0f) ? coef : -coef;
            r = fmaf(csel, __ldg(&iw1[(m << 7) + k]), r);
            segb[(g + 1) * SEGROW + fidx] = r * w2k;
        }
    }
    // zero pad slots (8 per row: gap npos..nposp-1 and tail)
    {
        int d = nposp - npos;
        float* segb = g_AB + (size_t)b * SEGB;
        for (int idx = tx; idx < 129 * 8; idx += 256) {
            int g = idx >> 3, e = idx & 7;
            int sl = (e < d) ? (npos + e) : (nposp + (HID - npos) + (e - d));
            int fa = g * SEGROW + ((sl >> 2) << 3) + (sl & 3);
            segb[fa] = 0.0f;
            segb[fa + 4] = 0.0f;
        }
    }

    // ---- deterministic counting sort of points by segment ----
    {
        int p0 = warp * PR;
        int pend = min(p0 + PR, ROWS);
        for (int p = p0 + lane; p < pend; p += 32) {
            int i = p / S1, j = p - i * S1;
            float tbi = xb * (steps_s[i] + 1.0f) * 0.5f;
            float rem = xmax - tbi;
            float s = fmaf(rem, (steps_s[j] + 1.0f) * 0.5f, tbi);
            atomicAdd(&cnt2[warp * 132 + seg_of(s, bp_s)], 1);
        }
    }
    __syncthreads();
    if (tx < 129) {
        int t = 0;
        #pragma unroll
        for (int w = 0; w < 8; w++) t += cnt2[w * 132 + tx];
        offs_s[tx] = t;
    }
    __syncthreads();
    if (tx == 0) {
        int run = 0;
        for (int g = 0; g <= 128; ++g) { int t = offs_s[g]; offs_s[g] = run; run += t; }
    }
    __syncthreads();
    if (tx < 129) {
        int run = offs_s[tx];
        #pragma unroll
        for (int w = 0; w < 8; w++) { woff[w * 132 + tx] = run; run += cnt2[w * 132 + tx]; }
    }
    __syncthreads();
    {
        int* myoff = woff + warp * 132;
        int p0 = warp * PR;
        int pend = min(p0 + PR, ROWS);
        for (int base = p0; base < pend; base += 32) {
            int p = base + lane;
            bool valid = (p < pend);
            float s = 0.0f, wt = 0.0f;
            int g;
            if (valid) {
                int i = p / S1, j = p - i * S1;
                float tbi = xb * (steps_s[i] + 1.0f) * 0.5f;
                float rem = xmax - tbi;
                s = fmaf(rem, (steps_s[j] + 1.0f) * 0.5f, tbi);
                wt = cc_s[i] * cc_s[j] * rem * 0.5f;
                g = seg_of(s, bp_s);
            } else {
                g = 512 + lane;   // distinct dummies
            }
            unsigned mm = __match_any_sync(0xffffffffu, g);
            int rank_in = __popc(mm & ((1u << lane) - 1u));
            int leader = __ffs(mm) - 1;
            int boff = 0;
            if (lane == leader && valid) {
                boff = myoff[g];
                myoff[g] = boff + __popc(mm);
            }
            boff = __shfl_sync(0xffffffffu, boff, leader);
            if (valid)
                g_meta[b * ROWS + boff + rank_in] =
                    make_float4(s, wt, __int_as_float(g), 0.0f);
        }
    }
}

// ===================== quad (+ fused final combine) =====================
__global__ void __launch_bounds__(128)
quad_kernel(const float* __restrict__ x, const float* __restrict__ ib2,
            float* __restrict__ out)
{
    __shared__ float red_s[128];
    const int b     = blockIdx.x >> 3;     // CPB = 8
    const int chunk = blockIdx.x & 7;
    const int tx    = threadIdx.x;
    const int np4   = g_nposp >> 2;
    const float ib2v = __ldg(ib2);

    const float4* ABb = (const float4*)(g_AB + (size_t)b * SEGB);

    const int q0   = chunk * PTS;
    const int qend = min(q0 + PTS, ROWS);
    float acc = 0.0f;
    for (int q = q0 + tx; q < qend; q += 128) {
        float4 m = __ldg(&g_meta[b * ROWS + q]);
        const float4* row = ABb + __float_as_int(m.z) * (SEGROW / 4);
        float s = m.x;
        float pr0 = 0.0f, pr1 = 0.0f;
        int kq = 0;
        #pragma unroll 4
        for (; kq < np4; ++kq) {
            float4 a = __ldg(row + 2 * kq), bb = __ldg(row + 2 * kq + 1);
            pr0 += fmaxf(fmaf(s, a.x, bb.x), 0.0f) + fmaxf(fmaf(s, a.y, bb.y), 0.0f);
            pr1 += fmaxf(fmaf(s, a.z, bb.z), 0.0f) + fmaxf(fmaf(s, a.w, bb.w), 0.0f);
        }
        #pragma unroll 4
        for (; kq < NK4; ++kq) {
            float4 a = __ldg(row + 2 * kq), bb = __ldg(row + 2 * kq + 1);
            pr0 += fminf(fmaf(s, a.x, bb.x), 0.0f) + fminf(fmaf(s, a.y, bb.y), 0.0f);
            pr1 += fminf(fmaf(s, a.z, bb.z), 0.0f) + fminf(fmaf(s, a.w, bb.w), 0.0f);
        }
        float z = (pr0 + pr1) + ib2v;
        float f = (z > 0.0f) ? (z + 1.0f) : expf(z);   // elu(z)+1
        acc = fmaf(f, m.y, acc);
    }
    red_s[tx] = acc;
    __syncthreads();
    for (int o = 64; o > 0; o >>= 1) {
        if (tx < o) red_s[tx] += red_s[tx + o];
        __syncthreads();
    }
    if (tx == 0) {
        g_part[b * CPB + chunk] = red_s[0];
        __threadfence();
        int old = atomicAdd(&g_done[b], 1);
        if (old == CPB - 1) {
            __threadfence();
            float sum = 0.0f;
            #pragma unroll
            for (int c = 0; c < CPB; c++) sum += __ldcg(&g_part[b * CPB + c]);
            float outer = sum * __ldg(&x[b]) * 0.5f;
            out[b] = expf(__ldcg(&g_osc[2 * b + 1])) * outer + __ldcg(&g_osc[2 * b]);
        }
    }
}

// ===================== launch =====================
extern "C" void kernel_launch(void* const* d_in, const int* in_sizes, int n_in,
                              void* d_out, int out_size) {
    const float* x   = (const float*)d_in[0];
    const float* h   = (const float*)d_in[1];
    const float* iw0 = (const float*)d_in[2];
    const float* ib0 = (const float*)d_in[3];
    const float* iw1 = (const float*)d_in[4];
    const float* ib1 = (const float*)d_in[5];
    const float* iw2 = (const float*)d_in[6];
    const float* ib2 = (const float*)d_in[7];
    const float* nw0 = (const float*)d_in[8];
    const float* nb0 = (const float*)d_in[9];
    const float* nw1 = (const float*)d_in[10];
    const float* nb1 = (const float*)d_in[11];
    const float* nw2 = (const float*)d_in[12];
    const float* nb2 = (const float*)d_in[13];
    float* out = (float*)d_out;
    (void)in_sizes; (void)n_in; (void)out_size;

    build_kernel<<<BSZ, 256>>>(x, h, iw0, ib0, iw1, ib1, iw2,
                               nw0, nb0, nw1, nb1, nw2, nb2);
    quad_kernel<<<BSZ * CPB, 128>>>(x, ib2, out);
}

// round 11
// speedup vs baseline: 1.7776x; 1.2815x over previous
#include <cuda_runtime.h>
#include <math.h>

#define BSZ 256
#define IND 64
#define HID 128
#define NB 50
#define S1 51
#define ROWS (S1 * S1)            // 2601
#define SEGROW 272                // interleaved A/B row: 34 * (A4 + B4) floats
#define NK4 34
#define SEGB (129 * SEGROW)       // 35088 floats per b
#define CPB 4
#define PPC ((ROWS + CPB - 1) / CPB)   // 651
#define PR  326                   // points per scatter-warp in build (8 warps)
#define SMAX 40                   // max segment rows staged per strip
#define TH0 0.06283185307179586f  // pi/50

// ---------------- global scratch ----------------
__device__ int   g_nposp;
__device__ __align__(16) float g_AB[BSZ * SEGB];   // ~36 MB interleaved A/B
__device__ float4 g_meta[BSZ * ROWS];
__device__ int   g_offs[BSZ * 130];                // segment start offsets + sentinel
__device__ float g_part[BSZ * CPB];
__device__ float g_osc[BSZ * 2];
__device__ int   g_done[BSZ];

__device__ __forceinline__ int seg_of(float s, const float* bp_s) {
    int g = 0;
    #pragma unroll
    for (int stp = 64; stp >= 1; stp >>= 1) {
        int cand = g + stp;
        if (cand <= 128 && bp_s[cand - 1] < s) g = cand;
    }
    return g;
}

// ===================== build: fully self-contained per-b setup =====================
__global__ void __launch_bounds__(256, 3)
build_kernel(const float* __restrict__ x,   const float* __restrict__ h,
             const float* __restrict__ iw0, const float* __restrict__ ib0,
             const float* __restrict__ iw1, const float* __restrict__ ib1,
             const float* __restrict__ iw2,
             const float* __restrict__ nw0, const float* __restrict__ nb0,
             const float* __restrict__ nw1, const float* __restrict__ nb1,
             const float* __restrict__ nw2, const float* __restrict__ nb2)
{
    __shared__ float h_s[64];
    __shared__ float base_s[HID];
    __shared__ float w0_s[HID];
    __shared__ float bp_s[HID];
    __shared__ int   mi_s[HID];
    __shared__ float iw2_s[HID];
    __shared__ int   iperm_s[HID];
    __shared__ float a_s[HID];
    __shared__ float a2_s[HID];
    __shared__ float red_s[8];
    __shared__ float steps_s[S1 + 1];
    __shared__ float cc_s[S1 + 1];
    __shared__ float redx_s[256];
    __shared__ int   cnt2[8 * 132];
    __shared__ int   woff[8 * 132];
    __shared__ int   offs_s[132];
    __shared__ int   wc_s[4];
    __shared__ int   npos_s, nposp_s;
    __shared__ float xmax_s;

    const int tx = threadIdx.x;
    const int warp = tx >> 5, lane = tx & 31;
    const int b  = blockIdx.x;
    const float xb = x[b];

    if (tx < IND - 1) h_s[tx] = h[b * (IND - 1) + tx];
    if (tx < HID) iw2_s[tx] = iw2[tx];
    for (int i = tx; i < 8 * 132; i += 256) cnt2[i] = 0;
    if (tx == 0) g_done[b] = 0;

    // xmax: max over all b of x_b*(u in [0,1]) -> max(max_b x, 0) + 10
    redx_s[tx] = x[tx];
    __syncthreads();
    for (int o = 128; o > 0; o >>= 1) {
        if (tx < o) redx_s[tx] = fmaxf(redx_s[tx], redx_s[tx + o]);
        __syncthreads();
    }
    if (tx == 0) xmax_s = fmaxf(redx_s[0], 0.0f) + 10.0f;

    // steps + cc (float recurrences)
    if (tx < S1) steps_s[tx] = cosf((float)tx * TH0);
    __syncthreads();
    if (tx < S1) {
        float sv = steps_s[tx];
        float c1 = fmaf(2.0f * sv, sv, -1.0f);
        float cm2 = 1.0f, cm1 = c1;
        float sum = 1.0f;
        #pragma unroll
        for (int ie = 1; ie <= 25; ++ie) {
            float cv = (ie == 1) ? c1 : fmaf(2.0f * c1, cm1, -cm2);
            if (ie > 1) { cm2 = cm1; cm1 = cv; }
            float W = 2.0f / (1.0f - 4.0f * (float)(ie * ie));
            sum = fmaf(cv, W, sum);
        }
        float v = sum * (2.0f / (float)NB);
        if (tx == 0 || tx == NB) v *= 0.5f;
        cc_s[tx] = v;
    }

    // iperm via ballot scan
    {
        bool pos = false; unsigned bal = 0;
        if (tx < HID) {
            pos = (iw2_s[tx] >= 0.0f);
            bal = __ballot_sync(0xffffffffu, pos);
            if (lane == 0) wc_s[warp] = __popc(bal);
        }
        __syncthreads();
        if (tx == 0) {
            int np = wc_s[0] + wc_s[1] + wc_s[2] + wc_s[3];
            npos_s = np;
            nposp_s = (np + 3) & ~3;
            if (b == 0) g_nposp = nposp_s;
        }
        __syncthreads();
        if (tx < HID) {
            unsigned lt = (1u << lane) - 1u;
            int posbef = __popc(bal & lt);
            int prefpos = 0;
            #pragma unroll
            for (int wi = 0; wi < 4; ++wi) if (wi < warp) prefpos += wc_s[wi];
            int slot;
            if (pos) slot = prefpos + posbef;
            else     slot = nposp_s + (warp * 32 - prefpos) + (lane - posbef);
            iperm_s[tx] = slot;
        }
    }

    const float xmax = xmax_s;
    const int npos  = npos_s;
    const int nposp = nposp_s;

    // base/breakpoints (tx<128) | nmlp layer0 (128..255)
    if (tx < HID) {
        float acc = ib0[tx];
        #pragma unroll 7
        for (int d = 0; d < IND - 1; ++d)
            acc = fmaf(h_s[d], iw0[(d + 1) * HID + tx], acc);
        base_s[tx] = acc;
        float w0m = iw0[tx];
        w0_s[tx] = w0m;
        float ss;
        if (w0m != 0.0f) ss = -acc / w0m;
        else ss = (acc > 0.0f) ? __int_as_float(0x7f800000) : __int_as_float(0xff800000);
        bp_s[tx] = ss;
        mi_s[tx] = tx;
    } else {
        int k = tx - 128;
        float acc = nb0[k];
        #pragma unroll 7
        for (int d = 0; d < IND - 1; ++d)
            acc = fmaf(h_s[d], nw0[d * HID + k], acc);
        a_s[k] = fmaxf(acc, 0.0f);
    }
    __syncthreads();
    if (tx < HID) {
        float acc = nb1[tx];
        #pragma unroll 8
        for (int m = 0; m < HID; ++m)
            acc = fmaf(a_s[m], nw1[m * HID + tx], acc);
        a2_s[tx] = fmaxf(acc, 0.0f);
    }
    __syncthreads();
    {
        int o  = tx >> 7;
        int n2 = tx & 127;
        float p = a2_s[n2] * nw2[n2 * 2 + o];
        #pragma unroll
        for (int off = 16; off >= 1; off >>= 1)
            p += __shfl_xor_sync(0xffffffffu, p, off);
        if (lane == 0) red_s[warp] = p;
    }
    __syncthreads();
    if (tx == 0)   g_osc[2 * b]     = nb2[0] + ((red_s[0] + red_s[1]) + (red_s[2] + red_s[3]));
    if (tx == 128) g_osc[2 * b + 1] = nb2[1] + ((red_s[4] + red_s[5]) + (red_s[6] + red_s[7]));
    __syncthreads();

    // bitonic sort of 128 breakpoints (ascending, payload mi)
    for (int kk = 2; kk <= 128; kk <<= 1) {
        for (int j = kk >> 1; j > 0; j >>= 1) {
            if (tx < 128) {
                int ixj = tx ^ j;
                if (ixj > tx) {
                    float a = bp_s[tx], c = bp_s[ixj];
                    bool up = ((tx & kk) == 0);
                    if ((a > c) == up) {
                        bp_s[tx] = c; bp_s[ixj] = a;
                        int t2 = mi_s[tx]; mi_s[tx] = mi_s[ixj]; mi_s[ixj] = t2;
                    }
                }
            }
            __syncthreads();
        }
    }

    // single-pass builder: iw1 from L2, iw2 factored to the store
    {
        const int k = tx & 127;
        const bool isA = (tx < 128);
        const int kp = iperm_s[k];
        const float w2k = iw2_s[k];
        float* segb = g_AB + (size_t)b * SEGB;
        const int fidx = ((kp >> 2) << 3) + (kp & 3) + (isA ? 0 : 4);
        float r = isA ? 0.0f : ib1[k];
        #pragma unroll 8
        for (int m = 0; m < HID; ++m) {
            float w0m = w0_s[m];
            float coef = isA ? w0m : base_s[m];
            coef = (w0m <= 0.0f) ? coef : 0.0f;
            r = fmaf(coef, __ldg(&iw1[(m << 7) + k]), r);
        }
        segb[fidx] = r * w2k;
        #pragma unroll 8
        for (int g = 0; g < 128; ++g) {
            int m = mi_s[g];
            float w0m = w0_s[m];
            float coef = isA ? w0m : base_s[m];
            float csel = (w0m > 0.0f) ? coef : -coef;
            r = fmaf(csel, __ldg(&iw1[(m << 7) + k]), r);
            segb[(g + 1) * SEGROW + fidx] = r * w2k;
        }
    }
    // zero pad slots
    {
        int d = nposp - npos;
        float* segb = g_AB + (size_t)b * SEGB;
        for (int idx = tx; idx < 129 * 8; idx += 256) {
            int g = idx >> 3, e = idx & 7;
            int sl = (e < d) ? (npos + e) : (nposp + (HID - npos) + (e - d));
            int fa = g * SEGROW + ((sl >> 2) << 3) + (sl & 3);
            segb[fa] = 0.0f;
            segb[fa + 4] = 0.0f;
        }
    }

    // deterministic counting sort of points by segment
    {
        int p0 = warp * PR;
        int pend = min(p0 + PR, ROWS);
        for (int p = p0 + lane; p < pend; p += 32) {
            int i = p / S1, j = p - i * S1;
            float tbi = xb * (steps_s[i] + 1.0f) * 0.5f;
            float rem = xmax - tbi;
            float s = fmaf(rem, (steps_s[j] + 1.0f) * 0.5f, tbi);
            atomicAdd(&cnt2[warp * 132 + seg_of(s, bp_s)], 1);
        }
    }
    __syncthreads();
    if (tx < 129) {
        int t = 0;
        #pragma unroll
        for (int w = 0; w < 8; w++) t += cnt2[w * 132 + tx];
        offs_s[tx] = t;
    }
    __syncthreads();
    if (tx == 0) {
        int run = 0;
        for (int g = 0; g <= 128; ++g) { int t = offs_s[g]; offs_s[g] = run; run += t; }
        offs_s[129] = run;   // == ROWS sentinel
    }
    __syncthreads();
    if (tx < 130) g_offs[b * 130 + tx] = offs_s[tx];
    if (tx < 129) {
        int run = offs_s[tx];
        #pragma unroll
        for (int w = 0; w < 8; w++) { woff[w * 132 + tx] = run; run += cnt2[w * 132 + tx]; }
    }
    __syncthreads();
    {
        int* myoff = woff + warp * 132;
        int p0 = warp * PR;
        int pend = min(p0 + PR, ROWS);
        for (int base = p0; base < pend; base += 32) {
            int p = base + lane;
            bool valid = (p < pend);
            float s = 0.0f, wt = 0.0f;
            int g;
            if (valid) {
                int i = p / S1, j = p - i * S1;
                float tbi = xb * (steps_s[i] + 1.0f) * 0.5f;
                float rem = xmax - tbi;
                s = fmaf(rem, (steps_s[j] + 1.0f) * 0.5f, tbi);
                wt = cc_s[i] * cc_s[j] * rem * 0.5f;
                g = seg_of(s, bp_s);
            } else {
                g = 512 + lane;
            }
            unsigned mm = __match_any_sync(0xffffffffu, g);
            int rank_in = __popc(mm & ((1u << lane) - 1u));
            int leader = __ffs(mm) - 1;
            int boff = 0;
            if (lane == leader && valid) {
                boff = myoff[g];
                myoff[g] = boff + __popc(mm);
            }
            boff = __shfl_sync(0xffffffffu, boff, leader);
            if (valid)
                g_meta[b * ROWS + boff + rank_in] =
                    make_float4(s, wt, __int_as_float(g), 0.0f);
        }
    }
}

// ===================== quad: strip-staged smem rows (+ fused combine) =====================
__global__ void __launch_bounds__(256, 4)
quad_kernel(const float* __restrict__ x, const float* __restrict__ ib2,
            float* __restrict__ out)
{
    __shared__ float4 rows_s[SMAX * (SEGROW / 4)];   // 40 * 68 float4 = 43.5 KB
    __shared__ float red_s[256];
    __shared__ int info_s[2];

    const int b     = blockIdx.x >> 2;     // CPB = 4
    const int chunk = blockIdx.x & 3;
    const int tx    = threadIdx.x;
    const int np4   = g_nposp >> 2;
    const float ib2v = __ldg(ib2);

    const float4* ABb   = (const float4*)(g_AB + (size_t)b * SEGB);
    const float4* metab = &g_meta[b * ROWS];

    const int q0   = chunk * PPC;
    const int qend = min(q0 + PPC, ROWS);

    float acc = 0.0f;
    int qcur = q0;
    while (qcur < qend) {
        __syncthreads();   // protect rows_s from previous strip's readers
        if (tx == 0) {
            float4 m0 = __ldg(&metab[qcur]);
            int gb = __float_as_int(m0.z);
            info_s[0] = gb;
            int ghi = min(gb + SMAX, 129);
            info_s[1] = g_offs[b * 130 + ghi];
        }
        __syncthreads();
        const int g_base = info_s[0];
        const int NR = min(g_base + SMAX, 129) - g_base;
        const int strip_end = min(info_s[1], qend);
        // cooperative row staging (coalesced)
        const float4* src = ABb + g_base * (SEGROW / 4);
        for (int i = tx; i < NR * (SEGROW / 4); i += 256)
            rows_s[i] = __ldg(src + i);
        __syncthreads();
        // point loop over this strip
        for (int q = qcur + tx; q < strip_end; q += 256) {
            float4 m = __ldg(&metab[q]);
            const float4* row = rows_s + (__float_as_int(m.z) - g_base) * (SEGROW / 4);
            float s = m.x;
            float pr0 = 0.0f, pr1 = 0.0f;
            int kq = 0;
            #pragma unroll 4
            for (; kq < np4; ++kq) {
                float4 a = row[2 * kq], bb = row[2 * kq + 1];
                pr0 += fmaxf(fmaf(s, a.x, bb.x), 0.0f) + fmaxf(fmaf(s, a.y, bb.y), 0.0f);
                pr1 += fmaxf(fmaf(s, a.z, bb.z), 0.0f) + fmaxf(fmaf(s, a.w, bb.w), 0.0f);
            }
            #pragma unroll 4
            for (; kq < NK4; ++kq) {
                float4 a = row[2 * kq], bb = row[2 * kq + 1];
                pr0 += fminf(fmaf(s, a.x, bb.x), 0.0f) + fminf(fmaf(s, a.y, bb.y), 0.0f);
                pr1 += fminf(fmaf(s, a.z, bb.z), 0.0f) + fminf(fmaf(s, a.w, bb.w), 0.0f);
            }
            float z = (pr0 + pr1) + ib2v;
            float f = (z > 0.0f) ? (z + 1.0f) : __expf(z);   // elu(z)+1
            acc = fmaf(f, m.y, acc);
        }
        qcur = strip_end;
    }

    red_s[tx] = acc;
    __syncthreads();
    for (int o = 128; o > 0; o >>= 1) {
        if (tx < o) red_s[tx] += red_s[tx + o];
        __syncthreads();
    }
    if (tx == 0) {
        g_part[b * CPB + chunk] = red_s[0];
        __threadfence();
        int old = atomicAdd(&g_done[b], 1);
        if (old == CPB - 1) {
            __threadfence();
            float sum = 0.0f;
            #pragma unroll
            for (int c = 0; c < CPB; c++) sum += __ldcg(&g_part[b * CPB + c]);
            float outer = sum * __ldg(&x[b]) * 0.5f;
            out[b] = expf(__ldcg(&g_osc[2 * b + 1])) * outer + __ldcg(&g_osc[2 * b]);
        }
    }
}

// ===================== launch =====================
extern "C" void kernel_launch(void* const* d_in, const int* in_sizes, int n_in,
                              void* d_out, int out_size) {
    const float* x   = (const float*)d_in[0];
    const float* h   = (const float*)d_in[1];
    const float* iw0 = (const float*)d_in[2];
    const float* ib0 = (const float*)d_in[3];
    const float* iw1 = (const float*)d_in[4];
    const float* ib1 = (const float*)d_in[5];
    const float* iw2 = (const float*)d_in[6];
    const float* ib2 = (const float*)d_in[7];
    const float* nw0 = (const float*)d_in[8];
    const float* nb0 = (const float*)d_in[9];
    const float* nw1 = (const float*)d_in[10];
    const float* nb1 = (const float*)d_in[11];
    const float* nw2 = (const float*)d_in[12];
    const float* nb2 = (const float*)d_in[13];
    float* out = (float*)d_out;
    (void)in_sizes; (void)n_in; (void)out_size;

    build_kernel<<<BSZ, 256>>>(x, h, iw0, ib0, iw1, ib1, iw2,
                               nw0, nb0, nw1, nb1, nw2, nb2);
    quad_kernel<<<BSZ * CPB, 256>>>(x, ib2, out);
}